// round 5
// baseline (speedup 1.0000x reference)
#include <cuda_runtime.h>
#include <cstdint>

// Problem constants (shapes are fixed by the dataset)
#define MAXN 100000
#define MAXE 1600000
#define HDIM 64
#define SCAN_B 1024

// ---------------- scratch (no allocations allowed -> __device__ globals) ----
__device__ int   g_deg[MAXN];                 // zero at load; re-zeroed by scanA
__device__ float g_dinv[MAXN];
__device__ int   g_rowstart[MAXN + 1];
__device__ int   g_cursor[MAXN];
__device__ int   g_esrc[MAXE];
__device__ int   g_blocksum[1024];
__device__ int   g_blockoff[1024];
__device__ float g_hs[(size_t)MAXN * HDIM];
__device__ float g_y[(size_t)MAXN * HDIM];

// ---------------- f32x2 helpers (Blackwell packed fp32) ---------------------
__device__ __forceinline__ unsigned long long pack2(float x, float y) {
    unsigned long long r;
    asm("mov.b64 %0, {%1,%2};" : "=l"(r) : "f"(x), "f"(y));
    return r;
}
__device__ __forceinline__ unsigned long long ffma2(unsigned long long a,
                                                    unsigned long long b,
                                                    unsigned long long c) {
    unsigned long long d;
    asm("fma.rn.f32x2 %0, %1, %2, %3;" : "=l"(d) : "l"(a), "l"(b), "l"(c));
    return d;
}
__device__ __forceinline__ unsigned long long add2(unsigned long long a,
                                                   unsigned long long b) {
    unsigned long long d;
    asm("add.rn.f32x2 %0, %1, %2;" : "=l"(d) : "l"(a), "l"(b));
    return d;
}
__device__ __forceinline__ unsigned long long mul2(unsigned long long a,
                                                   unsigned long long b) {
    unsigned long long d;
    asm("mul.rn.f32x2 %0, %1, %2;" : "=l"(d) : "l"(a), "l"(b));
    return d;
}
__device__ __forceinline__ float2 unpack2(unsigned long long v) {
    float2 f;
    asm("mov.b64 {%0,%1}, %2;" : "=f"(f.x), "=f"(f.y) : "l"(v));
    return f;
}

// ---------------- CSR build --------------------------------------------------
__global__ void count_deg_kernel(const int* __restrict__ dst, int e) {
    int i = blockIdx.x * blockDim.x + threadIdx.x;
    if (i < e) atomicAdd(&g_deg[dst[i]], 1);
}

// Phase A: per-block exclusive scan of g_deg; fused dinv; re-zero deg.
__global__ void __launch_bounds__(SCAN_B)
scanA_kernel(int n) {
    __shared__ int sh[SCAN_B];
    const int t = threadIdx.x;
    const int i = blockIdx.x * SCAN_B + t;
    const int v = (i < n) ? g_deg[i] : 0;
    if (i < n) {
        g_dinv[i] = rsqrtf((float)v + 1.0f);
        g_deg[i] = 0;                       // ready for next replay
    }
    sh[t] = v;
    __syncthreads();
    int acc = v;
#pragma unroll
    for (int off = 1; off < SCAN_B; off <<= 1) {
        int u = (t >= off) ? sh[t - off] : 0;
        __syncthreads();
        acc += u;
        sh[t] = acc;
        __syncthreads();
    }
    if (i < n) g_rowstart[i] = acc - v;     // local exclusive
    if (t == SCAN_B - 1) g_blocksum[blockIdx.x] = acc;
}

// Phase B: single-block exclusive scan of block sums (nb <= 1024).
__global__ void __launch_bounds__(1024)
scanB_kernel(int nb) {
    __shared__ int sh[1024];
    const int t = threadIdx.x;
    const int v = (t < nb) ? g_blocksum[t] : 0;
    sh[t] = v;
    __syncthreads();
    int acc = v;
#pragma unroll
    for (int off = 1; off < 1024; off <<= 1) {
        int u = (t >= off) ? sh[t - off] : 0;
        __syncthreads();
        acc += u;
        sh[t] = acc;
        __syncthreads();
    }
    if (t < nb) g_blockoff[t] = acc - v;    // exclusive
}

// Phase C: add block offsets; write rowstart and cursor (+sentinel).
__global__ void __launch_bounds__(SCAN_B)
scanC_kernel(int n, int e) {
    const int i = blockIdx.x * SCAN_B + threadIdx.x;
    if (i < n) {
        const int r = g_rowstart[i] + g_blockoff[blockIdx.x];
        g_rowstart[i] = r;
        g_cursor[i]   = r;
    }
    if (i == 0) g_rowstart[n] = e;
}

__global__ void place_kernel(const int* __restrict__ src,
                             const int* __restrict__ dst, int e) {
    int i = blockIdx.x * blockDim.x + threadIdx.x;
    if (i < e) {
        int d = dst[i];
        int pos = atomicAdd(&g_cursor[d], 1);
        g_esrc[pos] = src[i];
    }
}

// ---------------- GEMM: hs[row] = (X[row] @ W) * dinv[row] ------------------
// One thread per row. W is read via uniform-address LDG: all 32 lanes hit the
// same 128B line -> 1 L1tex wavefront per LDG.128 (vs 4 crossbar-cyc for the
// smem broadcast it replaces). W (<=32KB) stays L1-resident. Per warp-k:
// 16 wavefronts + 32 FFMA2 -> ~16 cyc, FFMA2-pipe/L1-balanced.
template <int KDIM>
__global__ void __launch_bounds__(128)
gemm_hs_kernel(const float* __restrict__ X, const float* __restrict__ W, int n) {
    const int row = blockIdx.x * 128 + threadIdx.x;
    if (row >= n) return;

    unsigned long long acc[32];
#pragma unroll
    for (int p = 0; p < 32; p++) acc[p] = 0ull;

    const float4* xr = (const float4*)(X + (size_t)row * KDIM);
    const ulonglong2* Wv = (const ulonglong2*)W;   // 16 x 16B per W row

#pragma unroll 1
    for (int kc = 0; kc < KDIM / 16; kc++) {
        float4 a4[4];
#pragma unroll
        for (int q = 0; q < 4; q++) a4[q] = __ldg(&xr[kc * 4 + q]);
        const float* av = reinterpret_cast<const float*>(a4);
#pragma unroll
        for (int kk = 0; kk < 16; kk++) {
            const float a = av[kk];
            const unsigned long long ap = pack2(a, a);
            const ulonglong2* wk = Wv + (size_t)(kc * 16 + kk) * 16;
#pragma unroll
            for (int p = 0; p < 16; p++) {
                const ulonglong2 w = __ldg(&wk[p]);   // uniform addr: 1 wavefront
                acc[2 * p]     = ffma2(ap, w.x, acc[2 * p]);
                acc[2 * p + 1] = ffma2(ap, w.y, acc[2 * p + 1]);
            }
        }
    }

    const float dv = __ldg(&g_dinv[row]);
    const unsigned long long dp = pack2(dv, dv);
    float2* op = (float2*)(g_hs + (size_t)row * HDIM);
#pragma unroll
    for (int p = 0; p < 32; p++) op[p] = unpack2(mul2(acc[p], dp));
}

// ---------------- gather + self-loop + bias + LayerNorm + GELU (+ head) -----
// One warp per node. lane l owns columns (2l, 2l+1) as a packed f32x2 (u64).
// 4-wide unrolled edge loop: 4 loads in flight, packed adds.
template <bool FINAL>
__global__ void __launch_bounds__(256)
gather_finalize_kernel(const float* __restrict__ b, const float* __restrict__ g,
                       const float* __restrict__ be, const float* __restrict__ Wh,
                       const float* __restrict__ bh, float* __restrict__ out,
                       int n) {
    const int warp = (blockIdx.x * blockDim.x + threadIdx.x) >> 5;
    const int lane = threadIdx.x & 31;
    if (warp >= n) return;
    const int node = warp;

    const int s0 = g_rowstart[node];
    const int s1 = g_rowstart[node + 1];

    const unsigned long long* hsp = (const unsigned long long*)g_hs;

    unsigned long long a0 = 0ull, a1 = 0ull, a2 = 0ull, a3 = 0ull;

    for (int e = s0; e < s1; e += 32) {
        const int cnt = min(32, s1 - e);
        const int s = (lane < cnt) ? __ldg(&g_esrc[e + lane]) : 0;
        int i = 0;
        for (; i + 4 <= cnt; i += 4) {
            const int sa = __shfl_sync(0xffffffffu, s, i);
            const int sb = __shfl_sync(0xffffffffu, s, i + 1);
            const int sc = __shfl_sync(0xffffffffu, s, i + 2);
            const int sd = __shfl_sync(0xffffffffu, s, i + 3);
            const unsigned long long va = __ldg(&hsp[(size_t)sa * 32 + lane]);
            const unsigned long long vb = __ldg(&hsp[(size_t)sb * 32 + lane]);
            const unsigned long long vc = __ldg(&hsp[(size_t)sc * 32 + lane]);
            const unsigned long long vd = __ldg(&hsp[(size_t)sd * 32 + lane]);
            a0 = add2(a0, va);
            a1 = add2(a1, vb);
            a2 = add2(a2, vc);
            a3 = add2(a3, vd);
        }
        for (; i < cnt; i++) {
            const int sa = __shfl_sync(0xffffffffu, s, i);
            a0 = add2(a0, __ldg(&hsp[(size_t)sa * 32 + lane]));
        }
    }

    // total = edges + self-loop term
    unsigned long long tot = add2(add2(a0, a1), add2(a2, a3));
    tot = add2(tot, __ldg(&hsp[(size_t)node * 32 + lane]));
    const float2 t2 = unpack2(tot);

    const float dv = g_dinv[node];
    float v0 = dv * t2.x + __ldg(&b[2 * lane]);
    float v1 = dv * t2.y + __ldg(&b[2 * lane + 1]);

    // LayerNorm over 64 values (2 per lane)
    float s  = v0 + v1;
    float sq = v0 * v0 + v1 * v1;
#pragma unroll
    for (int o = 16; o > 0; o >>= 1) {
        s  += __shfl_xor_sync(0xffffffffu, s, o);
        sq += __shfl_xor_sync(0xffffffffu, sq, o);
    }
    const float mu   = s * (1.0f / 64.0f);
    float var        = sq * (1.0f / 64.0f) - mu * mu;
    const float rstd = rsqrtf(var + 1e-5f);

    float u0 = (v0 - mu) * rstd * __ldg(&g[2 * lane]) + __ldg(&be[2 * lane]);
    float u1 = (v1 - mu) * rstd * __ldg(&g[2 * lane + 1]) + __ldg(&be[2 * lane + 1]);

    // exact-erf GELU
    u0 = 0.5f * u0 * (1.0f + erff(u0 * 0.70710678118654752f));
    u1 = 0.5f * u1 * (1.0f + erff(u1 * 0.70710678118654752f));

    if (FINAL) {
        float p = u0 * __ldg(&Wh[2 * lane]) + u1 * __ldg(&Wh[2 * lane + 1]);
#pragma unroll
        for (int o = 16; o > 0; o >>= 1) p += __shfl_xor_sync(0xffffffffu, p, o);
        if (lane == 0) out[node] = p + __ldg(&bh[0]);
    } else {
        ((float2*)out)[(size_t)node * 32 + lane] = make_float2(u0, u1);
    }
}

// ---------------- launch -----------------------------------------------------
extern "C" void kernel_launch(void* const* d_in, const int* in_sizes, int n_in,
                              void* d_out, int out_size) {
    const float* x   = (const float*)d_in[0];
    const int*   ei  = (const int*)d_in[1];
    const float* W1  = (const float*)d_in[2];
    const float* b1  = (const float*)d_in[3];
    const float* g1  = (const float*)d_in[4];
    const float* be1 = (const float*)d_in[5];
    const float* W2  = (const float*)d_in[6];
    const float* b2  = (const float*)d_in[7];
    const float* g2  = (const float*)d_in[8];
    const float* be2 = (const float*)d_in[9];
    const float* W3  = (const float*)d_in[10];
    const float* b3  = (const float*)d_in[11];
    const float* g3  = (const float*)d_in[12];
    const float* be3 = (const float*)d_in[13];
    const float* Wh  = (const float*)d_in[14];
    const float* bh  = (const float*)d_in[15];
    float* out = (float*)d_out;

    const int n = in_sizes[0] / 128;
    const int e = in_sizes[1] / 2;
    const int* srcs = ei;
    const int* dsts = ei + e;

    static float* y = nullptr;
    if (!y) cudaGetSymbolAddress((void**)&y, g_y);

    const int EB = (e + 255) / 256;
    const int SB = (n + SCAN_B - 1) / SCAN_B;  // scan blocks (<= 98)
    const int GB = (n + 127) / 128;            // gemm blocks
    const int WB = (n + 7) / 8;                // gather blocks (8 warps/block)

    // CSR build (deg is zeroed at module load and re-zeroed by scanA)
    count_deg_kernel<<<EB, 256>>>(dsts, e);
    scanA_kernel<<<SB, SCAN_B>>>(n);           // + fused dinv + deg re-zero
    scanB_kernel<<<1, 1024>>>(SB);
    scanC_kernel<<<SB, SCAN_B>>>(n, e);        // + fused cursor init
    place_kernel<<<EB, 256>>>(srcs, dsts, e);

    // Layer 1 (IN=128)
    gemm_hs_kernel<128><<<GB, 128>>>(x, W1, n);
    gather_finalize_kernel<false><<<WB, 256>>>(b1, g1, be1, nullptr, nullptr, y, n);
    // Layer 2 (IN=64)
    gemm_hs_kernel<64><<<GB, 128>>>(y, W2, n);
    gather_finalize_kernel<false><<<WB, 256>>>(b2, g2, be2, nullptr, nullptr, y, n);
    // Layer 3 (IN=64) + fused head
    gemm_hs_kernel<64><<<GB, 128>>>(y, W3, n);
    gather_finalize_kernel<true><<<WB, 256>>>(b3, g3, be3, Wh, bh, out, n);
}

// round 6
// speedup vs baseline: 1.7263x; 1.7263x over previous
#include <cuda_runtime.h>
#include <cstdint>

// Problem constants (shapes are fixed by the dataset)
#define MAXN 100000
#define MAXE 1600000
#define HDIM 64
#define SCAN_B 1024

// ---------------- scratch (no allocations allowed -> __device__ globals) ----
__device__ int   g_deg[MAXN];                 // zero at load; re-zeroed by scanA
__device__ float g_dinv[MAXN];
__device__ int   g_rowstart[MAXN + 1];
__device__ int   g_cursor[MAXN];
__device__ int   g_esrc[MAXE];
__device__ int   g_blocksum[1024];
__device__ int   g_blockoff[1024];
__device__ float g_hs[(size_t)MAXN * HDIM];
__device__ float g_y[(size_t)MAXN * HDIM];

// ---------------- f32x2 helpers (Blackwell packed fp32) ---------------------
__device__ __forceinline__ unsigned long long pack2(float x, float y) {
    unsigned long long r;
    asm("mov.b64 %0, {%1,%2};" : "=l"(r) : "f"(x), "f"(y));
    return r;
}
__device__ __forceinline__ unsigned long long ffma2(unsigned long long a,
                                                    unsigned long long b,
                                                    unsigned long long c) {
    unsigned long long d;
    asm("fma.rn.f32x2 %0, %1, %2, %3;" : "=l"(d) : "l"(a), "l"(b), "l"(c));
    return d;
}
__device__ __forceinline__ unsigned long long add2(unsigned long long a,
                                                   unsigned long long b) {
    unsigned long long d;
    asm("add.rn.f32x2 %0, %1, %2;" : "=l"(d) : "l"(a), "l"(b));
    return d;
}
__device__ __forceinline__ unsigned long long mul2(unsigned long long a,
                                                   unsigned long long b) {
    unsigned long long d;
    asm("mul.rn.f32x2 %0, %1, %2;" : "=l"(d) : "l"(a), "l"(b));
    return d;
}
__device__ __forceinline__ float2 unpack2(unsigned long long v) {
    float2 f;
    asm("mov.b64 {%0,%1}, %2;" : "=f"(f.x), "=f"(f.y) : "l"(v));
    return f;
}
__device__ __forceinline__ void lds_v2u64(unsigned addr, unsigned long long& a,
                                          unsigned long long& b) {
    asm("ld.shared.v2.u64 {%0,%1}, [%2];" : "=l"(a), "=l"(b) : "r"(addr));
}

// ---------------- CSR build --------------------------------------------------
__global__ void count_deg_kernel(const int* __restrict__ dst, int e) {
    int i = blockIdx.x * blockDim.x + threadIdx.x;
    if (i < e) atomicAdd(&g_deg[dst[i]], 1);
}

// Phase A: per-block exclusive scan of g_deg; fused dinv; re-zero deg.
__global__ void __launch_bounds__(SCAN_B)
scanA_kernel(int n) {
    __shared__ int sh[SCAN_B];
    const int t = threadIdx.x;
    const int i = blockIdx.x * SCAN_B + t;
    const int v = (i < n) ? g_deg[i] : 0;
    if (i < n) {
        g_dinv[i] = rsqrtf((float)v + 1.0f);
        g_deg[i] = 0;                       // ready for next replay
    }
    sh[t] = v;
    __syncthreads();
    int acc = v;
#pragma unroll
    for (int off = 1; off < SCAN_B; off <<= 1) {
        int u = (t >= off) ? sh[t - off] : 0;
        __syncthreads();
        acc += u;
        sh[t] = acc;
        __syncthreads();
    }
    if (i < n) g_rowstart[i] = acc - v;     // local exclusive
    if (t == SCAN_B - 1) g_blocksum[blockIdx.x] = acc;
}

// Phase B: single-block exclusive scan of block sums (nb <= 1024).
__global__ void __launch_bounds__(1024)
scanB_kernel(int nb) {
    __shared__ int sh[1024];
    const int t = threadIdx.x;
    const int v = (t < nb) ? g_blocksum[t] : 0;
    sh[t] = v;
    __syncthreads();
    int acc = v;
#pragma unroll
    for (int off = 1; off < 1024; off <<= 1) {
        int u = (t >= off) ? sh[t - off] : 0;
        __syncthreads();
        acc += u;
        sh[t] = acc;
        __syncthreads();
    }
    if (t < nb) g_blockoff[t] = acc - v;    // exclusive
}

// Phase C: add block offsets; write rowstart and cursor (+sentinel).
__global__ void __launch_bounds__(SCAN_B)
scanC_kernel(int n, int e) {
    const int i = blockIdx.x * SCAN_B + threadIdx.x;
    if (i < n) {
        const int r = g_rowstart[i] + g_blockoff[blockIdx.x];
        g_rowstart[i] = r;
        g_cursor[i]   = r;
    }
    if (i == 0) g_rowstart[n] = e;
}

__global__ void place_kernel(const int* __restrict__ src,
                             const int* __restrict__ dst, int e) {
    int i = blockIdx.x * blockDim.x + threadIdx.x;
    if (i < e) {
        int d = dst[i];
        int pos = atomicAdd(&g_cursor[d], 1);
        g_esrc[pos] = src[i];
    }
}

// ---------------- GEMM: hs[row] = (X[row] @ W) * dinv[row] ------------------
// TWO rows per thread: the 16 broadcast LDS.128 of W per k feed 64 FFMA2
// (2 rows x 32), halving the binding LDS-instruction count per FLOP vs the
// 1-row version. W broadcast from smem (conflict-free, N=1).
template <int KDIM>
__global__ void __launch_bounds__(128, 1)
gemm_hs_kernel(const float* __restrict__ X, const float* __restrict__ W, int n) {
    __shared__ float Ws[KDIM * HDIM];
    for (int i = threadIdx.x; i < KDIM * HDIM / 4; i += 128)
        ((float4*)Ws)[i] = ((const float4*)W)[i];
    __syncthreads();

    const int row0 = blockIdx.x * 256 + threadIdx.x;
    const int row1 = row0 + 128;
    if (row0 >= n) return;
    const bool has1 = (row1 < n);

    unsigned long long acc0[32], acc1[32];
#pragma unroll
    for (int p = 0; p < 32; p++) { acc0[p] = 0ull; acc1[p] = 0ull; }

    const float4* xr0 = (const float4*)(X + (size_t)row0 * KDIM);
    const float4* xr1 = (const float4*)(X + (size_t)(has1 ? row1 : row0) * KDIM);
    const unsigned wsh = (unsigned)__cvta_generic_to_shared(Ws);

#pragma unroll 1
    for (int kc = 0; kc < KDIM / 4; kc++) {
        const float4 a0 = xr0[kc];
        const float4 a1 = xr1[kc];
        const float* av0 = reinterpret_cast<const float*>(&a0);
        const float* av1 = reinterpret_cast<const float*>(&a1);
#pragma unroll
        for (int kk = 0; kk < 4; kk++) {
            const unsigned long long ap0 = pack2(av0[kk], av0[kk]);
            const unsigned long long ap1 = pack2(av1[kk], av1[kk]);
            const unsigned baddr = wsh + (unsigned)((kc * 4 + kk) * HDIM) * 4u;
#pragma unroll
            for (int p = 0; p < 16; p++) {
                unsigned long long b0, b1;
                lds_v2u64(baddr + p * 16u, b0, b1);
                acc0[2 * p]     = ffma2(ap0, b0, acc0[2 * p]);
                acc0[2 * p + 1] = ffma2(ap0, b1, acc0[2 * p + 1]);
                acc1[2 * p]     = ffma2(ap1, b0, acc1[2 * p]);
                acc1[2 * p + 1] = ffma2(ap1, b1, acc1[2 * p + 1]);
            }
        }
    }

    {
        const float dv = __ldg(&g_dinv[row0]);
        const unsigned long long dp = pack2(dv, dv);
        float2* op = (float2*)(g_hs + (size_t)row0 * HDIM);
#pragma unroll
        for (int p = 0; p < 32; p++) op[p] = unpack2(mul2(acc0[p], dp));
    }
    if (has1) {
        const float dv = __ldg(&g_dinv[row1]);
        const unsigned long long dp = pack2(dv, dv);
        float2* op = (float2*)(g_hs + (size_t)row1 * HDIM);
#pragma unroll
        for (int p = 0; p < 32; p++) op[p] = unpack2(mul2(acc1[p], dp));
    }
}

// ---------------- gather + self-loop + bias + LayerNorm + GELU (+ head) -----
// One warp per node. lane l owns columns (2l, 2l+1) as a packed f32x2 (u64).
// 4-wide unrolled edge loop: 4 loads in flight, packed adds.
template <bool FINAL>
__global__ void __launch_bounds__(256)
gather_finalize_kernel(const float* __restrict__ b, const float* __restrict__ g,
                       const float* __restrict__ be, const float* __restrict__ Wh,
                       const float* __restrict__ bh, float* __restrict__ out,
                       int n) {
    const int warp = (blockIdx.x * blockDim.x + threadIdx.x) >> 5;
    const int lane = threadIdx.x & 31;
    if (warp >= n) return;
    const int node = warp;

    const int s0 = g_rowstart[node];
    const int s1 = g_rowstart[node + 1];

    const unsigned long long* hsp = (const unsigned long long*)g_hs;

    unsigned long long a0 = 0ull, a1 = 0ull, a2 = 0ull, a3 = 0ull;

    for (int e = s0; e < s1; e += 32) {
        const int cnt = min(32, s1 - e);
        const int s = (lane < cnt) ? __ldg(&g_esrc[e + lane]) : 0;
        int i = 0;
        for (; i + 4 <= cnt; i += 4) {
            const int sa = __shfl_sync(0xffffffffu, s, i);
            const int sb = __shfl_sync(0xffffffffu, s, i + 1);
            const int sc = __shfl_sync(0xffffffffu, s, i + 2);
            const int sd = __shfl_sync(0xffffffffu, s, i + 3);
            const unsigned long long va = __ldg(&hsp[(size_t)sa * 32 + lane]);
            const unsigned long long vb = __ldg(&hsp[(size_t)sb * 32 + lane]);
            const unsigned long long vc = __ldg(&hsp[(size_t)sc * 32 + lane]);
            const unsigned long long vd = __ldg(&hsp[(size_t)sd * 32 + lane]);
            a0 = add2(a0, va);
            a1 = add2(a1, vb);
            a2 = add2(a2, vc);
            a3 = add2(a3, vd);
        }
        for (; i < cnt; i++) {
            const int sa = __shfl_sync(0xffffffffu, s, i);
            a0 = add2(a0, __ldg(&hsp[(size_t)sa * 32 + lane]));
        }
    }

    // total = edges + self-loop term
    unsigned long long tot = add2(add2(a0, a1), add2(a2, a3));
    tot = add2(tot, __ldg(&hsp[(size_t)node * 32 + lane]));
    const float2 t2 = unpack2(tot);

    const float dv = g_dinv[node];
    float v0 = dv * t2.x + __ldg(&b[2 * lane]);
    float v1 = dv * t2.y + __ldg(&b[2 * lane + 1]);

    // LayerNorm over 64 values (2 per lane)
    float s  = v0 + v1;
    float sq = v0 * v0 + v1 * v1;
#pragma unroll
    for (int o = 16; o > 0; o >>= 1) {
        s  += __shfl_xor_sync(0xffffffffu, s, o);
        sq += __shfl_xor_sync(0xffffffffu, sq, o);
    }
    const float mu   = s * (1.0f / 64.0f);
    float var        = sq * (1.0f / 64.0f) - mu * mu;
    const float rstd = rsqrtf(var + 1e-5f);

    float u0 = (v0 - mu) * rstd * __ldg(&g[2 * lane]) + __ldg(&be[2 * lane]);
    float u1 = (v1 - mu) * rstd * __ldg(&g[2 * lane + 1]) + __ldg(&be[2 * lane + 1]);

    // exact-erf GELU
    u0 = 0.5f * u0 * (1.0f + erff(u0 * 0.70710678118654752f));
    u1 = 0.5f * u1 * (1.0f + erff(u1 * 0.70710678118654752f));

    if (FINAL) {
        float p = u0 * __ldg(&Wh[2 * lane]) + u1 * __ldg(&Wh[2 * lane + 1]);
#pragma unroll
        for (int o = 16; o > 0; o >>= 1) p += __shfl_xor_sync(0xffffffffu, p, o);
        if (lane == 0) out[node] = p + __ldg(&bh[0]);
    } else {
        ((float2*)out)[(size_t)node * 32 + lane] = make_float2(u0, u1);
    }
}

// ---------------- launch -----------------------------------------------------
extern "C" void kernel_launch(void* const* d_in, const int* in_sizes, int n_in,
                              void* d_out, int out_size) {
    const float* x   = (const float*)d_in[0];
    const int*   ei  = (const int*)d_in[1];
    const float* W1  = (const float*)d_in[2];
    const float* b1  = (const float*)d_in[3];
    const float* g1  = (const float*)d_in[4];
    const float* be1 = (const float*)d_in[5];
    const float* W2  = (const float*)d_in[6];
    const float* b2  = (const float*)d_in[7];
    const float* g2  = (const float*)d_in[8];
    const float* be2 = (const float*)d_in[9];
    const float* W3  = (const float*)d_in[10];
    const float* b3  = (const float*)d_in[11];
    const float* g3  = (const float*)d_in[12];
    const float* be3 = (const float*)d_in[13];
    const float* Wh  = (const float*)d_in[14];
    const float* bh  = (const float*)d_in[15];
    float* out = (float*)d_out;

    const int n = in_sizes[0] / 128;
    const int e = in_sizes[1] / 2;
    const int* srcs = ei;
    const int* dsts = ei + e;

    static float* y = nullptr;
    if (!y) cudaGetSymbolAddress((void**)&y, g_y);

    const int EB = (e + 255) / 256;
    const int SB = (n + SCAN_B - 1) / SCAN_B;  // scan blocks (<= 98)
    const int GB = (n + 255) / 256;            // gemm blocks (2 rows/thread)
    const int WB = (n + 7) / 8;                // gather blocks (8 warps/block)

    // CSR build (deg is zeroed at module load and re-zeroed by scanA)
    count_deg_kernel<<<EB, 256>>>(dsts, e);
    scanA_kernel<<<SB, SCAN_B>>>(n);           // + fused dinv + deg re-zero
    scanB_kernel<<<1, 1024>>>(SB);
    scanC_kernel<<<SB, SCAN_B>>>(n, e);        // + fused cursor init
    place_kernel<<<EB, 256>>>(srcs, dsts, e);

    // Layer 1 (IN=128)
    gemm_hs_kernel<128><<<GB, 128>>>(x, W1, n);
    gather_finalize_kernel<false><<<WB, 256>>>(b1, g1, be1, nullptr, nullptr, y, n);
    // Layer 2 (IN=64)
    gemm_hs_kernel<64><<<GB, 128>>>(y, W2, n);
    gather_finalize_kernel<false><<<WB, 256>>>(b2, g2, be2, nullptr, nullptr, y, n);
    // Layer 3 (IN=64) + fused head
    gemm_hs_kernel<64><<<GB, 128>>>(y, W3, n);
    gather_finalize_kernel<true><<<WB, 256>>>(b3, g3, be3, Wh, bh, out, n);
}

// round 8
// speedup vs baseline: 2.0060x; 1.1620x over previous
#include <cuda_runtime.h>
#include <cuda_fp16.h>
#include <cstdint>

// Problem constants (shapes are fixed by the dataset)
#define MAXN 100000
#define MAXE 1600000
#define HDIM 64
#define SCAN_B 1024

// ---------------- scratch (no allocations allowed -> __device__ globals) ----
__device__ int    g_deg[MAXN];                 // zero at load; re-zeroed by scanA
__device__ float  g_dinv[MAXN];
__device__ int    g_rowstart[MAXN + 1];
__device__ int    g_cursor[MAXN];
__device__ int    g_esrc[MAXE];
__device__ int    g_blocksum[1024];
__device__ int    g_blockoff[1024];
__device__ __half g_hs[(size_t)MAXN * HDIM];   // fp16: 128B/row -> 2 edges/warp
__device__ float  g_y[(size_t)MAXN * HDIM];

// ---------------- f32x2 helpers (Blackwell packed fp32) ---------------------
__device__ __forceinline__ unsigned long long pack2(float x, float y) {
    unsigned long long r;
    asm("mov.b64 %0, {%1,%2};" : "=l"(r) : "f"(x), "f"(y));
    return r;
}
__device__ __forceinline__ unsigned long long ffma2(unsigned long long a,
                                                    unsigned long long b,
                                                    unsigned long long c) {
    unsigned long long d;
    asm("fma.rn.f32x2 %0, %1, %2, %3;" : "=l"(d) : "l"(a), "l"(b), "l"(c));
    return d;
}
__device__ __forceinline__ unsigned long long mul2(unsigned long long a,
                                                   unsigned long long b) {
    unsigned long long d;
    asm("mul.rn.f32x2 %0, %1, %2;" : "=l"(d) : "l"(a), "l"(b));
    return d;
}
__device__ __forceinline__ float2 unpack2(unsigned long long v) {
    float2 f;
    asm("mov.b64 {%0,%1}, %2;" : "=f"(f.x), "=f"(f.y) : "l"(v));
    return f;
}
__device__ __forceinline__ void lds_v2u64(unsigned addr, unsigned long long& a,
                                          unsigned long long& b) {
    asm("ld.shared.v2.u64 {%0,%1}, [%2];" : "=l"(a), "=l"(b) : "r"(addr));
}
// add 4 fp16 values (one u64) into 4 fp32 accumulators
__device__ __forceinline__ void acc_h4(unsigned long long v, float4& a) {
    const unsigned lo = (unsigned)v, hi = (unsigned)(v >> 32);
    const __half2 h0 = *reinterpret_cast<const __half2*>(&lo);
    const __half2 h1 = *reinterpret_cast<const __half2*>(&hi);
    const float2 f0 = __half22float2(h0);
    const float2 f1 = __half22float2(h1);
    a.x += f0.x; a.y += f0.y; a.z += f1.x; a.w += f1.y;
}

// ---------------- CSR build --------------------------------------------------
__global__ void count_deg_kernel(const int* __restrict__ dst, int e) {
    int i = blockIdx.x * blockDim.x + threadIdx.x;
    if (i < e) atomicAdd(&g_deg[dst[i]], 1);
}

// Phase A: per-block exclusive scan of g_deg; fused dinv; re-zero deg.
__global__ void __launch_bounds__(SCAN_B)
scanA_kernel(int n) {
    __shared__ int sh[SCAN_B];
    const int t = threadIdx.x;
    const int i = blockIdx.x * SCAN_B + t;
    const int v = (i < n) ? g_deg[i] : 0;
    if (i < n) {
        g_dinv[i] = rsqrtf((float)v + 1.0f);
        g_deg[i] = 0;                       // ready for next replay
    }
    sh[t] = v;
    __syncthreads();
    int acc = v;
#pragma unroll
    for (int off = 1; off < SCAN_B; off <<= 1) {
        int u = (t >= off) ? sh[t - off] : 0;
        __syncthreads();
        acc += u;
        sh[t] = acc;
        __syncthreads();
    }
    if (i < n) g_rowstart[i] = acc - v;     // local exclusive
    if (t == SCAN_B - 1) g_blocksum[blockIdx.x] = acc;
}

// Phase B: single-block exclusive scan of block sums (nb <= 1024).
__global__ void __launch_bounds__(1024)
scanB_kernel(int nb) {
    __shared__ int sh[1024];
    const int t = threadIdx.x;
    const int v = (t < nb) ? g_blocksum[t] : 0;
    sh[t] = v;
    __syncthreads();
    int acc = v;
#pragma unroll
    for (int off = 1; off < 1024; off <<= 1) {
        int u = (t >= off) ? sh[t - off] : 0;
        __syncthreads();
        acc += u;
        sh[t] = acc;
        __syncthreads();
    }
    if (t < nb) g_blockoff[t] = acc - v;    // exclusive
}

// Phase C: add block offsets; write rowstart and cursor (+sentinel).
__global__ void __launch_bounds__(SCAN_B)
scanC_kernel(int n, int e) {
    const int i = blockIdx.x * SCAN_B + threadIdx.x;
    if (i < n) {
        const int r = g_rowstart[i] + g_blockoff[blockIdx.x];
        g_rowstart[i] = r;
        g_cursor[i]   = r;
    }
    if (i == 0) g_rowstart[n] = e;
}

__global__ void place_kernel(const int* __restrict__ src,
                             const int* __restrict__ dst, int e) {
    int i = blockIdx.x * blockDim.x + threadIdx.x;
    if (i < e) {
        int d = dst[i];
        int pos = atomicAdd(&g_cursor[d], 1);
        g_esrc[pos] = src[i];
    }
}

// ---------------- GEMM: hs[row] = fp16( (X[row] @ W) * dinv[row] ) ----------
// TWO rows per thread; W broadcast from smem; fp32 f32x2 accumulation,
// converted to fp16 only at the store.
template <int KDIM>
__global__ void __launch_bounds__(128, 1)
gemm_hs_kernel(const float* __restrict__ X, const float* __restrict__ W, int n) {
    __shared__ float Ws[KDIM * HDIM];
    for (int i = threadIdx.x; i < KDIM * HDIM / 4; i += 128)
        ((float4*)Ws)[i] = ((const float4*)W)[i];
    __syncthreads();

    const int row0 = blockIdx.x * 256 + threadIdx.x;
    const int row1 = row0 + 128;
    if (row0 >= n) return;
    const bool has1 = (row1 < n);

    unsigned long long acc0[32], acc1[32];
#pragma unroll
    for (int p = 0; p < 32; p++) { acc0[p] = 0ull; acc1[p] = 0ull; }

    const float4* xr0 = (const float4*)(X + (size_t)row0 * KDIM);
    const float4* xr1 = (const float4*)(X + (size_t)(has1 ? row1 : row0) * KDIM);
    const unsigned wsh = (unsigned)__cvta_generic_to_shared(Ws);

#pragma unroll 1
    for (int kc = 0; kc < KDIM / 4; kc++) {
        const float4 a0 = xr0[kc];
        const float4 a1 = xr1[kc];
        const float* av0 = reinterpret_cast<const float*>(&a0);
        const float* av1 = reinterpret_cast<const float*>(&a1);
#pragma unroll
        for (int kk = 0; kk < 4; kk++) {
            const unsigned long long ap0 = pack2(av0[kk], av0[kk]);
            const unsigned long long ap1 = pack2(av1[kk], av1[kk]);
            const unsigned baddr = wsh + (unsigned)((kc * 4 + kk) * HDIM) * 4u;
#pragma unroll
            for (int p = 0; p < 16; p++) {
                unsigned long long b0, b1;
                lds_v2u64(baddr + p * 16u, b0, b1);
                acc0[2 * p]     = ffma2(ap0, b0, acc0[2 * p]);
                acc0[2 * p + 1] = ffma2(ap0, b1, acc0[2 * p + 1]);
                acc1[2 * p]     = ffma2(ap1, b0, acc1[2 * p]);
                acc1[2 * p + 1] = ffma2(ap1, b1, acc1[2 * p + 1]);
            }
        }
    }

    {
        const float dv = __ldg(&g_dinv[row0]);
        const unsigned long long dp = pack2(dv, dv);
        uint4* op = (uint4*)(g_hs + (size_t)row0 * HDIM);
#pragma unroll
        for (int v = 0; v < 8; v++) {
            uint4 w;
            __half2 h;
            h = __float22half2_rn(unpack2(mul2(acc0[4 * v + 0], dp))); w.x = *(unsigned*)&h;
            h = __float22half2_rn(unpack2(mul2(acc0[4 * v + 1], dp))); w.y = *(unsigned*)&h;
            h = __float22half2_rn(unpack2(mul2(acc0[4 * v + 2], dp))); w.z = *(unsigned*)&h;
            h = __float22half2_rn(unpack2(mul2(acc0[4 * v + 3], dp))); w.w = *(unsigned*)&h;
            op[v] = w;
        }
    }
    if (has1) {
        const float dv = __ldg(&g_dinv[row1]);
        const unsigned long long dp = pack2(dv, dv);
        uint4* op = (uint4*)(g_hs + (size_t)row1 * HDIM);
#pragma unroll
        for (int v = 0; v < 8; v++) {
            uint4 w;
            __half2 h;
            h = __float22half2_rn(unpack2(mul2(acc1[4 * v + 0], dp))); w.x = *(unsigned*)&h;
            h = __float22half2_rn(unpack2(mul2(acc1[4 * v + 1], dp))); w.y = *(unsigned*)&h;
            h = __float22half2_rn(unpack2(mul2(acc1[4 * v + 2], dp))); w.z = *(unsigned*)&h;
            h = __float22half2_rn(unpack2(mul2(acc1[4 * v + 3], dp))); w.w = *(unsigned*)&h;
            op[v] = w;
        }
    }
}

// ---------------- gather + self-loop + bias + LayerNorm + GELU (+ head) -----
// One warp per node, fp16 hs rows (128B). Half-warp h = lane>>4 handles edge
// i+h of each pair; lane q = lane&15 owns cols 4q..4q+3 (8B LDG), fp32 accum.
template <bool FINAL>
__global__ void __launch_bounds__(256)
gather_finalize_kernel(const float* __restrict__ b, const float* __restrict__ g,
                       const float* __restrict__ be, const float* __restrict__ Wh,
                       const float* __restrict__ bh, float* __restrict__ out,
                       int n) {
    const int warp = (blockIdx.x * blockDim.x + threadIdx.x) >> 5;
    const int lane = threadIdx.x & 31;
    if (warp >= n) return;
    const int node = warp;
    const int h = lane >> 4;       // which edge of the pair
    const int q = lane & 15;       // column block (4 halves = 8B)

    const int s0 = g_rowstart[node];
    const int s1 = g_rowstart[node + 1];

    const unsigned long long* hsp = (const unsigned long long*)g_hs;  // 16 u64/row

    float4 accA = make_float4(0.f, 0.f, 0.f, 0.f);
    float4 accB = make_float4(0.f, 0.f, 0.f, 0.f);

    for (int e = s0; e < s1; e += 32) {
        const int cnt = min(32, s1 - e);
        const int s = (lane < cnt) ? __ldg(&g_esrc[e + lane]) : 0;
        int i = 0;
        for (; i + 4 <= cnt; i += 4) {           // 2 pairs = 4 edges per iter
            const int sa = __shfl_sync(0xffffffffu, s, i + h);
            const int sb = __shfl_sync(0xffffffffu, s, i + 2 + h);
            const unsigned long long va = __ldg(&hsp[(size_t)sa * 16 + q]);
            const unsigned long long vb = __ldg(&hsp[(size_t)sb * 16 + q]);
            acc_h4(va, accA);
            acc_h4(vb, accB);
        }
        for (; i < cnt; i += 2) {                // pair tail
            const int idx = i + h;
            const int sa = __shfl_sync(0xffffffffu, s, idx & 31);
            if (idx < cnt)
                acc_h4(__ldg(&hsp[(size_t)sa * 16 + q]), accA);
        }
    }

    // self-loop term: add once (half-warp A only)
    if (h == 0)
        acc_h4(__ldg(&hsp[(size_t)node * 16 + q]), accA);

    accA.x += accB.x; accA.y += accB.y; accA.z += accB.z; accA.w += accB.w;
    // combine the two half-warps (same q in lane l and l^16)
    accA.x += __shfl_xor_sync(0xffffffffu, accA.x, 16);
    accA.y += __shfl_xor_sync(0xffffffffu, accA.y, 16);
    accA.z += __shfl_xor_sync(0xffffffffu, accA.z, 16);
    accA.w += __shfl_xor_sync(0xffffffffu, accA.w, 16);

    const float dv = g_dinv[node];
    const float4 b4 = __ldg(&((const float4*)b)[q]);
    float v0 = dv * accA.x + b4.x;
    float v1 = dv * accA.y + b4.y;
    float v2 = dv * accA.z + b4.z;
    float v3 = dv * accA.w + b4.w;

    // LayerNorm over 64 values (4 per lane, 16-lane groups; halves duplicate)
    float s  = v0 + v1 + v2 + v3;
    float sq = v0 * v0 + v1 * v1 + v2 * v2 + v3 * v3;
#pragma unroll
    for (int o = 8; o > 0; o >>= 1) {
        s  += __shfl_xor_sync(0xffffffffu, s, o);
        sq += __shfl_xor_sync(0xffffffffu, sq, o);
    }
    const float mu   = s * (1.0f / 64.0f);
    float var        = sq * (1.0f / 64.0f) - mu * mu;
    const float rstd = rsqrtf(var + 1e-5f);

    const float4 g4  = __ldg(&((const float4*)g)[q]);
    const float4 be4 = __ldg(&((const float4*)be)[q]);
    float u0 = (v0 - mu) * rstd * g4.x + be4.x;
    float u1 = (v1 - mu) * rstd * g4.y + be4.y;
    float u2 = (v2 - mu) * rstd * g4.z + be4.z;
    float u3 = (v3 - mu) * rstd * g4.w + be4.w;

    // exact-erf GELU
    const float k = 0.70710678118654752f;
    u0 = 0.5f * u0 * (1.0f + erff(u0 * k));
    u1 = 0.5f * u1 * (1.0f + erff(u1 * k));
    u2 = 0.5f * u2 * (1.0f + erff(u2 * k));
    u3 = 0.5f * u3 * (1.0f + erff(u3 * k));

    if (FINAL) {
        const float4 w4 = __ldg(&((const float4*)Wh)[q]);
        float p = u0 * w4.x + u1 * w4.y + u2 * w4.z + u3 * w4.w;
#pragma unroll
        for (int o = 8; o > 0; o >>= 1) p += __shfl_xor_sync(0xffffffffu, p, o);
        if (lane == 0) out[node] = p + __ldg(&bh[0]);
    } else {
        if (h == 0)
            ((float4*)out)[(size_t)node * 16 + q] = make_float4(u0, u1, u2, u3);
    }
}

// ---------------- launch -----------------------------------------------------
extern "C" void kernel_launch(void* const* d_in, const int* in_sizes, int n_in,
                              void* d_out, int out_size) {
    const float* x   = (const float*)d_in[0];
    const int*   ei  = (const int*)d_in[1];
    const float* W1  = (const float*)d_in[2];
    const float* b1  = (const float*)d_in[3];
    const float* g1  = (const float*)d_in[4];
    const float* be1 = (const float*)d_in[5];
    const float* W2  = (const float*)d_in[6];
    const float* b2  = (const float*)d_in[7];
    const float* g2  = (const float*)d_in[8];
    const float* be2 = (const float*)d_in[9];
    const float* W3  = (const float*)d_in[10];
    const float* b3  = (const float*)d_in[11];
    const float* g3  = (const float*)d_in[12];
    const float* be3 = (const float*)d_in[13];
    const float* Wh  = (const float*)d_in[14];
    const float* bh  = (const float*)d_in[15];
    float* out = (float*)d_out;

    const int n = in_sizes[0] / 128;
    const int e = in_sizes[1] / 2;
    const int* srcs = ei;
    const int* dsts = ei + e;

    static float* y = nullptr;
    if (!y) cudaGetSymbolAddress((void**)&y, g_y);

    const int EB = (e + 255) / 256;
    const int SB = (n + SCAN_B - 1) / SCAN_B;  // scan blocks (<= 98)
    const int GB = (n + 255) / 256;            // gemm blocks (2 rows/thread)
    const int WB = (n + 7) / 8;                // gather blocks (8 warps/block)

    // CSR build (deg is zeroed at module load and re-zeroed by scanA)
    count_deg_kernel<<<EB, 256>>>(dsts, e);
    scanA_kernel<<<SB, SCAN_B>>>(n);           // + fused dinv + deg re-zero
    scanB_kernel<<<1, 1024>>>(SB);
    scanC_kernel<<<SB, SCAN_B>>>(n, e);        // + fused cursor init
    place_kernel<<<EB, 256>>>(srcs, dsts, e);

    // Layer 1 (IN=128)
    gemm_hs_kernel<128><<<GB, 128>>>(x, W1, n);
    gather_finalize_kernel<false><<<WB, 256>>>(b1, g1, be1, nullptr, nullptr, y, n);
    // Layer 2 (IN=64)
    gemm_hs_kernel<64><<<GB, 128>>>(y, W2, n);
    gather_finalize_kernel<false><<<WB, 256>>>(b2, g2, be2, nullptr, nullptr, y, n);
    // Layer 3 (IN=64) + fused head
    gemm_hs_kernel<64><<<GB, 128>>>(y, W3, n);
    gather_finalize_kernel<true><<<WB, 256>>>(b3, g3, be3, Wh, bh, out, n);
}